// round 12
// baseline (speedup 1.0000x reference)
#include <cuda_runtime.h>

#define B_DIM 256
#define T_DIM 64
#define D_DIM 2048
#define THRESHOLD 0.99f
#define EPSILON 0.01f

#define THREADS 128
#define D4 (D_DIM / 4)                    // 512 float4 per row
#define BLOCKS_PER_B 4                    // 4 chunks of 128 float4 columns
#define PF 4                              // prefetch depth (covers h<=3: ~96%)

// ---------------------------------------------------------------------------
// Sparse ACT kernel, fully thread-local weight math (no shuffles/ballots/
// syncs on the fast path). weights[t]==0 for t>h; for U(0,1) halt probs
// P(h<=3) ~ 96%, so each thread derives h, remainder, weight-sum and the
// first-4 weights from two float4 loads. Rare h>=4 falls to a warp-uniform
// serial sweep (L2-hot). Summation order over nonzero terms matches the
// dense reference exactly (zeros contribute nothing).
// grid = B*4 = 1024, block = 128 (best measured shape).
// ---------------------------------------------------------------------------
__global__ __launch_bounds__(THREADS)
void act_sparse_kernel(const float* __restrict__ halt_probs,   // [B,T]
                       const float* __restrict__ outputs,      // [B,T,D]
                       const float* __restrict__ step_weights, // [B,T]
                       float* __restrict__ final_out,          // [B,D]
                       float* __restrict__ out_ponder,         // [B]
                       float* __restrict__ out_weights)        // [B,T]
{
    const int b     = blockIdx.x / BLOCKS_PER_B;
    const int chunk = blockIdx.x % BLOCKS_PER_B;
    const int tid   = threadIdx.x;

    const float* __restrict__ hp_row = halt_probs   + b * T_DIM;
    const float* __restrict__ sw_row = step_weights + b * T_DIM;

    // ---- head of the dependent chain: first-4 probs/weights ----
    const float4 hp4 = *reinterpret_cast<const float4*>(hp_row);
    const float4 sw4 = *reinterpret_cast<const float4*>(sw_row);

    const int d4 = chunk * THREADS + tid;   // float4 column in [0, D4)
    const float4* __restrict__ base =
        reinterpret_cast<const float4*>(outputs) + (size_t)b * T_DIM * D4 + d4;

    // ---- row prefetches (independent; consumed after weight math) ----
    float4 v0 = __ldcs(base + 0 * D4);
    float4 v1 = __ldcs(base + 1 * D4);
    float4 v2 = __ldcs(base + 2 * D4);
    float4 v3 = __ldcs(base + 3 * D4);

    // ---- thread-local halting computation ----
    const float c0 = hp4.x;
    const float c1 = c0 + hp4.y;
    const float c2 = c1 + hp4.z;
    const float c3 = c2 + hp4.w;

    int   h;
    float rem;

    if (c3 >= THRESHOLD) {
        // fast path: h in [0,3], fully closed-form
        if      (c0 >= THRESHOLD) { h = 0; rem = 1.0f - c0 + hp4.x; }
        else if (c1 >= THRESHOLD) { h = 1; rem = 1.0f - c1 + hp4.y; }
        else if (c2 >= THRESHOLD) { h = 2; rem = 1.0f - c2 + hp4.z; }
        else                      { h = 3; rem = 1.0f - c3 + hp4.w; }
    } else {
        // slow path (~4% of batches, warp-uniform): serial sweep, L2-hot
        float cum    = c3;
        float cum_at = 0.0f;
        float p_at   = 0.0f;
        int   hh     = T_DIM - 1;
        bool  found  = false;
        for (int t0 = 4; t0 < T_DIM; t0 += 4) {
            const float4 q = *reinterpret_cast<const float4*>(hp_row + t0);
            #pragma unroll
            for (int i = 0; i < 4; i++) {
                const float pi = (i == 0) ? q.x : (i == 1) ? q.y
                                : (i == 2) ? q.z : q.w;
                cum += pi;
                if (!found && cum >= THRESHOLD) {
                    found = true; hh = t0 + i; cum_at = cum; p_at = pi;
                }
            }
        }
        if (!found) { cum_at = cum; p_at = hp_row[T_DIM - 1]; }
        h   = hh;
        rem = 1.0f - cum_at + p_at;
    }

    // first-4 raw weights (zero beyond h)
    float w0 = ((0 < h) ? hp4.x : (0 == h) ? rem : 0.0f) * sw4.x;
    float w1 = ((1 < h) ? hp4.y : (1 == h) ? rem : 0.0f) * sw4.y;
    float w2 = ((2 < h) ? hp4.z : (2 == h) ? rem : 0.0f) * sw4.z;
    float w3 = ((3 < h) ? hp4.w : (3 == h) ? rem : 0.0f) * sw4.w;

    // weight sum: in-order over nonzero prefix (zeros add exactly nothing)
    float ws = ((w0 + w1) + w2) + w3;
    if (h >= PF) {
        for (int t = PF; t <= h; t++) {
            const float pt = (t < h) ? hp_row[t] : rem;
            ws += pt * sw_row[t];
        }
    }
    const float inv = 1.0f / fmaxf(ws, EPSILON);

    const float wa = w0 * inv;
    const float wb = w1 * inv;
    const float wc = w2 * inv;
    const float wd = w3 * inv;

    // ---- weights + ponder outputs: one block per batch (chunk 0) ----
    if (chunk == 0) {
        if (tid < T_DIM) {
            float w;
            if (tid < PF) {
                w = (tid == 0) ? wa : (tid == 1) ? wb : (tid == 2) ? wc : wd;
            } else {
                const float pt = (tid < h) ? hp_row[tid]
                                : (tid == h) ? rem : 0.0f;
                w = pt * sw_row[tid] * inv;
            }
            out_weights[b * T_DIM + tid] = w;
        }
        if (tid == 0) {
            float pc = wa * 1.0f + wb * 2.0f + wc * 3.0f + wd * 4.0f;
            for (int t = PF; t <= h; t++) {
                const float pt = (t < h) ? hp_row[t] : rem;
                pc += pt * sw_row[t] * inv * (float)(t + 1);
            }
            out_ponder[b] = pc;
        }
    }

    // ---- consume prefetched rows ----
    float4 acc;
    acc.x = wa * v0.x; acc.y = wa * v0.y; acc.z = wa * v0.z; acc.w = wa * v0.w;
    acc.x = fmaf(wb, v1.x, acc.x); acc.y = fmaf(wb, v1.y, acc.y);
    acc.z = fmaf(wb, v1.z, acc.z); acc.w = fmaf(wb, v1.w, acc.w);
    acc.x = fmaf(wc, v2.x, acc.x); acc.y = fmaf(wc, v2.y, acc.y);
    acc.z = fmaf(wc, v2.z, acc.z); acc.w = fmaf(wc, v2.w, acc.w);
    acc.x = fmaf(wd, v3.x, acc.x); acc.y = fmaf(wd, v3.y, acc.y);
    acc.z = fmaf(wd, v3.z, acc.z); acc.w = fmaf(wd, v3.w, acc.w);

    // ---- rare tail: h >= PF (~4% of batches), batched guarded loads ----
    for (int t0 = PF; t0 <= h; t0 += 4) {
        float4 u[4];
        #pragma unroll
        for (int i = 0; i < 4; i++) {
            const int t = t0 + i;
            u[i] = (t < T_DIM) ? __ldcs(base + (size_t)t * D4)
                               : make_float4(0.f, 0.f, 0.f, 0.f);
        }
        #pragma unroll
        for (int i = 0; i < 4; i++) {
            const int t = t0 + i;
            float wt = 0.0f;
            if (t <= h) {
                const float pt = (t < h) ? hp_row[t] : rem;   // L2-hot
                wt = pt * sw_row[t] * inv;
            }
            acc.x = fmaf(wt, u[i].x, acc.x);
            acc.y = fmaf(wt, u[i].y, acc.y);
            acc.z = fmaf(wt, u[i].z, acc.z);
            acc.w = fmaf(wt, u[i].w, acc.w);
        }
    }

    reinterpret_cast<float4*>(final_out)[(size_t)b * D4 + d4] = acc;
}

// ---------------------------------------------------------------------------
// kernel_launch
// Inputs: halt_probs [B,T,1], outputs [B,T,D], step_weights [B,T]  (fp32)
// Output: concat(final_output [B*D], ponder_cost [B], weights [B*T]) fp32
// ---------------------------------------------------------------------------
extern "C" void kernel_launch(void* const* d_in, const int* in_sizes, int n_in,
                              void* d_out, int out_size)
{
    const float* halt_probs   = (const float*)d_in[0];
    const float* outputs      = (const float*)d_in[1];
    const float* step_weights = (const float*)d_in[2];

    float* out         = (float*)d_out;
    float* final_out   = out;                              // [B,D]
    float* ponder_out  = out + (size_t)B_DIM * D_DIM;      // [B]
    float* weights_out = ponder_out + B_DIM;               // [B,T]

    act_sparse_kernel<<<B_DIM * BLOCKS_PER_B, THREADS>>>(
        halt_probs, outputs, step_weights,
        final_out, ponder_out, weights_out);
}

// round 14
// speedup vs baseline: 1.0370x; 1.0370x over previous
#include <cuda_runtime.h>

#define B_DIM 256
#define T_DIM 64
#define D_DIM 2048
#define THRESHOLD 0.99f
#define EPSILON 0.01f

#define THREADS 128
#define D4 (D_DIM / 4)                    // 512 float4 per row
#define BLOCKS_PER_B 4                    // 4 chunks of 128 float4 columns
#define PF 4                              // prefetch depth (covers h<=3: ~96%)

// ---------------------------------------------------------------------------
// Sparse ACT kernel. weights[t]==0 for t>h; for U(0,1) halt probs
// P(h<=3) ~ 96%, so only rows t<=h of the 128MB outputs tensor matter.
// Thread-local closed-form weight math (no shuffles/ballots/syncs); ALL
// independent global loads (4 output rows + halt4 + step4) are issued
// up front with NO intervening control flow, so they overlap in the
// L1tex queue (R12's regression came from a data-dependent branch
// separating them). Fast-path h/rem is pure select chains; the rare
// h>=4 slow path is a warp-uniform guarded override afterwards.
// grid = B*4 = 1024, block = 128 (best measured shape).
// ---------------------------------------------------------------------------
__global__ __launch_bounds__(THREADS)
void act_sparse_kernel(const float* __restrict__ halt_probs,   // [B,T]
                       const float* __restrict__ outputs,      // [B,T,D]
                       const float* __restrict__ step_weights, // [B,T]
                       float* __restrict__ final_out,          // [B,D]
                       float* __restrict__ out_ponder,         // [B]
                       float* __restrict__ out_weights)        // [B,T]
{
    const int b     = blockIdx.x / BLOCKS_PER_B;
    const int chunk = blockIdx.x % BLOCKS_PER_B;
    const int tid   = threadIdx.x;

    const float* __restrict__ hp_row = halt_probs   + b * T_DIM;
    const float* __restrict__ sw_row = step_weights + b * T_DIM;

    const int d4 = chunk * THREADS + tid;   // float4 column in [0, D4)
    const float4* __restrict__ base =
        reinterpret_cast<const float4*>(outputs) + (size_t)b * T_DIM * D4 + d4;

    // ---- ALL independent loads issued first, no control flow between ----
    const float4 v0  = __ldcs(base + 0 * D4);
    const float4 v1  = __ldcs(base + 1 * D4);
    const float4 v2  = __ldcs(base + 2 * D4);
    const float4 v3  = __ldcs(base + 3 * D4);
    const float4 hp4 = *reinterpret_cast<const float4*>(hp_row);
    const float4 sw4 = *reinterpret_cast<const float4*>(sw_row);

    // ---- branch-free fast-path halting computation (h in [0,3]) ----
    const float c0 = hp4.x;
    const float c1 = c0 + hp4.y;
    const float c2 = c1 + hp4.z;
    const float c3 = c2 + hp4.w;

    // select chains only; valid whenever c3 >= THRESHOLD (~96%)
    int   h   = (c0 >= THRESHOLD) ? 0
              : (c1 >= THRESHOLD) ? 1
              : (c2 >= THRESHOLD) ? 2 : 3;
    float rem = (c0 >= THRESHOLD) ? (1.0f - c0 + hp4.x)
              : (c1 >= THRESHOLD) ? (1.0f - c1 + hp4.y)
              : (c2 >= THRESHOLD) ? (1.0f - c2 + hp4.z)
              :                     (1.0f - c3 + hp4.w);

    // ---- rare slow path (~4%, warp-uniform): override h/rem ----
    if (c3 < THRESHOLD) {
        float cum    = c3;
        float cum_at = 0.0f;
        float p_at   = 0.0f;
        int   hh     = T_DIM - 1;
        bool  found  = false;
        for (int t0 = 4; t0 < T_DIM; t0 += 4) {
            const float4 q = *reinterpret_cast<const float4*>(hp_row + t0);
            #pragma unroll
            for (int i = 0; i < 4; i++) {
                const float pi = (i == 0) ? q.x : (i == 1) ? q.y
                                : (i == 2) ? q.z : q.w;
                cum += pi;
                if (!found && cum >= THRESHOLD) {
                    found = true; hh = t0 + i; cum_at = cum; p_at = pi;
                }
            }
        }
        if (!found) { cum_at = cum; p_at = hp_row[T_DIM - 1]; }
        h   = hh;
        rem = 1.0f - cum_at + p_at;
    }

    // first-4 raw weights (zero beyond h)
    float w0 = ((0 < h) ? hp4.x : (0 == h) ? rem : 0.0f) * sw4.x;
    float w1 = ((1 < h) ? hp4.y : (1 == h) ? rem : 0.0f) * sw4.y;
    float w2 = ((2 < h) ? hp4.z : (2 == h) ? rem : 0.0f) * sw4.z;
    float w3 = ((3 < h) ? hp4.w : (3 == h) ? rem : 0.0f) * sw4.w;

    // weight sum: in-order over nonzero prefix (zeros add exactly nothing)
    float ws = ((w0 + w1) + w2) + w3;
    if (h >= PF) {
        for (int t = PF; t <= h; t++) {
            const float pt = (t < h) ? hp_row[t] : rem;
            ws += pt * sw_row[t];
        }
    }
    const float inv = 1.0f / fmaxf(ws, EPSILON);

    const float wa = w0 * inv;
    const float wb = w1 * inv;
    const float wc = w2 * inv;
    const float wd = w3 * inv;

    // ---- consume prefetched rows ----
    float4 acc;
    acc.x = wa * v0.x; acc.y = wa * v0.y; acc.z = wa * v0.z; acc.w = wa * v0.w;
    acc.x = fmaf(wb, v1.x, acc.x); acc.y = fmaf(wb, v1.y, acc.y);
    acc.z = fmaf(wb, v1.z, acc.z); acc.w = fmaf(wb, v1.w, acc.w);
    acc.x = fmaf(wc, v2.x, acc.x); acc.y = fmaf(wc, v2.y, acc.y);
    acc.z = fmaf(wc, v2.z, acc.z); acc.w = fmaf(wc, v2.w, acc.w);
    acc.x = fmaf(wd, v3.x, acc.x); acc.y = fmaf(wd, v3.y, acc.y);
    acc.z = fmaf(wd, v3.z, acc.z); acc.w = fmaf(wd, v3.w, acc.w);

    // ---- rare tail: h >= PF (~4% of batches), batched guarded loads ----
    for (int t0 = PF; t0 <= h; t0 += 4) {
        float4 u[4];
        #pragma unroll
        for (int i = 0; i < 4; i++) {
            const int t = t0 + i;
            u[i] = (t < T_DIM) ? __ldcs(base + (size_t)t * D4)
                               : make_float4(0.f, 0.f, 0.f, 0.f);
        }
        #pragma unroll
        for (int i = 0; i < 4; i++) {
            const int t = t0 + i;
            float wt = 0.0f;
            if (t <= h) {
                const float pt = (t < h) ? hp_row[t] : rem;   // L2-hot
                wt = pt * sw_row[t] * inv;
            }
            acc.x = fmaf(wt, u[i].x, acc.x);
            acc.y = fmaf(wt, u[i].y, acc.y);
            acc.z = fmaf(wt, u[i].z, acc.z);
            acc.w = fmaf(wt, u[i].w, acc.w);
        }
    }

    reinterpret_cast<float4*>(final_out)[(size_t)b * D4 + d4] = acc;

    // ---- weights + ponder outputs: one block per batch (chunk 0) ----
    // After the store so it never delays the main dataflow.
    if (chunk == 0) {
        if (tid < T_DIM) {
            float w;
            if (tid < PF) {
                w = (tid == 0) ? wa : (tid == 1) ? wb : (tid == 2) ? wc : wd;
            } else {
                const float pt = (tid < h) ? hp_row[tid]
                                : (tid == h) ? rem : 0.0f;
                w = pt * sw_row[tid] * inv;
            }
            out_weights[b * T_DIM + tid] = w;
        }
        if (tid == 0) {
            float pc = wa * 1.0f + wb * 2.0f + wc * 3.0f + wd * 4.0f;
            for (int t = PF; t <= h; t++) {
                const float pt = (t < h) ? hp_row[t] : rem;
                pc += pt * sw_row[t] * inv * (float)(t + 1);
            }
            out_ponder[b] = pc;
        }
    }
}

// ---------------------------------------------------------------------------
// kernel_launch
// Inputs: halt_probs [B,T,1], outputs [B,T,D], step_weights [B,T]  (fp32)
// Output: concat(final_output [B*D], ponder_cost [B], weights [B*T]) fp32
// ---------------------------------------------------------------------------
extern "C" void kernel_launch(void* const* d_in, const int* in_sizes, int n_in,
                              void* d_out, int out_size)
{
    const float* halt_probs   = (const float*)d_in[0];
    const float* outputs      = (const float*)d_in[1];
    const float* step_weights = (const float*)d_in[2];

    float* out         = (float*)d_out;
    float* final_out   = out;                              // [B,D]
    float* ponder_out  = out + (size_t)B_DIM * D_DIM;      // [B]
    float* weights_out = ponder_out + B_DIM;               // [B,T]

    act_sparse_kernel<<<B_DIM * BLOCKS_PER_B, THREADS>>>(
        halt_probs, outputs, step_weights,
        final_out, ponder_out, weights_out);
}

// round 15
// speedup vs baseline: 1.2963x; 1.2500x over previous
#include <cuda_runtime.h>

#define B_DIM 256
#define T_DIM 64
#define D_DIM 2048
#define THRESHOLD 0.99f
#define EPSILON 0.01f

#define THREADS 128
#define D4 (D_DIM / 4)                    // 512 float4 per row
#define BLOCKS_PER_B 4                    // 4 chunks of 128 float4 columns
#define PF 4                              // prefetch depth (covers h<=3: ~96%)

// ---------------------------------------------------------------------------
// Sparse ACT kernel, barrier-free (measured-best configuration, R8).
// weights[t]==0 for t>h and h~2-3 for U(0,1) halt probs, so only rows
// t<=h of the 128MB outputs tensor are needed (~10MB). Each WARP
// redundantly computes the halting weights with a shuffle scan (no smem,
// no __syncthreads), overlapped with the 4-row prefetch issued FIRST.
// Rare h>=4 tail uses batched guarded loads. Summation order over nonzero
// terms matches the dense reference exactly (zeros contribute nothing).
// grid = B*4 = 1024, block = 128.
// ---------------------------------------------------------------------------
__global__ __launch_bounds__(THREADS)
void act_sparse_kernel(const float* __restrict__ halt_probs,   // [B,T]
                       const float* __restrict__ outputs,      // [B,T,D]
                       const float* __restrict__ step_weights, // [B,T]
                       float* __restrict__ final_out,          // [B,D]
                       float* __restrict__ out_ponder,         // [B]
                       float* __restrict__ out_weights)        // [B,T]
{
    const int b     = blockIdx.x / BLOCKS_PER_B;
    const int chunk = blockIdx.x % BLOCKS_PER_B;
    const int tid   = threadIdx.x;
    const int warp  = tid >> 5;
    const int lane  = tid & 31;
    const unsigned FULL = 0xFFFFFFFFu;

    const int d4 = chunk * THREADS + tid;   // float4 column in [0, D4)
    const float4* __restrict__ base =
        reinterpret_cast<const float4*>(outputs) + (size_t)b * T_DIM * D4 + d4;

    // ---- issue row prefetch FIRST (independent of weights) ----
    float4 v0 = __ldcs(base + 0 * D4);
    float4 v1 = __ldcs(base + 1 * D4);
    float4 v2 = __ldcs(base + 2 * D4);
    float4 v3 = __ldcs(base + 3 * D4);

    // ---- per-warp redundant weight computation (overlaps row loads) ----
    // lane owns t = 2*lane, 2*lane+1
    const float2 p  = reinterpret_cast<const float2*>(halt_probs   + b * T_DIM)[lane];
    const float2 sw = reinterpret_cast<const float2*>(step_weights + b * T_DIM)[lane];

    // inclusive scan of pair sums
    const float pairsum = p.x + p.y;
    float s = pairsum;
    #pragma unroll
    for (int o = 1; o < 32; o <<= 1) {
        float n = __shfl_up_sync(FULL, s, o);
        if (lane >= o) s += n;
    }
    const float excl = s - pairsum;     // cumsum before t=2*lane
    const float cum0 = excl + p.x;      // cumsum at t=2*lane
    const float cum1 = s;               // cumsum at t=2*lane+1

    const unsigned m0 = __ballot_sync(FULL, cum0 >= THRESHOLD);
    const unsigned m1 = __ballot_sync(FULL, cum1 >= THRESHOLD);
    const int c0 = m0 ? 2 * (__ffs(m0) - 1)     : T_DIM;
    const int c1 = m1 ? 2 * (__ffs(m1) - 1) + 1 : T_DIM;
    int h = min(c0, c1);
    if (h >= T_DIM) h = T_DIM - 1;

    const int   hl   = h >> 1;
    const int   hodd = h & 1;
    const float cum_at = __shfl_sync(FULL, hodd ? cum1 : cum0, hl);
    const float p_at   = __shfl_sync(FULL, hodd ? p.y  : p.x,  hl);
    const float rem    = 1.0f - cum_at + p_at;

    const int t0i = 2 * lane, t1i = 2 * lane + 1;
    float w0 = (t0i < h) ? p.x : ((t0i == h) ? rem : 0.0f);
    float w1 = (t1i < h) ? p.y : ((t1i == h) ? rem : 0.0f);
    w0 *= sw.x; w1 *= sw.y;

    float ws = w0 + w1;
    #pragma unroll
    for (int o = 16; o; o >>= 1) ws += __shfl_xor_sync(FULL, ws, o);
    const float inv = 1.0f / fmaxf(ws, EPSILON);
    w0 *= inv; w1 *= inv;

    // weights + ponder outputs: one warp of one block per batch
    if (chunk == 0 && warp == 0) {
        reinterpret_cast<float2*>(out_weights + b * T_DIM)[lane] =
            make_float2(w0, w1);
        float pc = w0 * (float)(t0i + 1) + w1 * (float)(t1i + 1);
        #pragma unroll
        for (int o = 16; o; o >>= 1) pc += __shfl_xor_sync(FULL, pc, o);
        if (lane == 0) out_ponder[b] = pc;
    }

    // broadcast first-4 weights from lanes 0,1
    const float wa = __shfl_sync(FULL, w0, 0);   // t=0
    const float wb = __shfl_sync(FULL, w1, 0);   // t=1
    const float wc = __shfl_sync(FULL, w0, 1);   // t=2
    const float wd = __shfl_sync(FULL, w1, 1);   // t=3

    // ---- consume prefetched rows ----
    float4 acc;
    acc.x = wa * v0.x; acc.y = wa * v0.y; acc.z = wa * v0.z; acc.w = wa * v0.w;
    acc.x = fmaf(wb, v1.x, acc.x); acc.y = fmaf(wb, v1.y, acc.y);
    acc.z = fmaf(wb, v1.z, acc.z); acc.w = fmaf(wb, v1.w, acc.w);
    acc.x = fmaf(wc, v2.x, acc.x); acc.y = fmaf(wc, v2.y, acc.y);
    acc.z = fmaf(wc, v2.z, acc.z); acc.w = fmaf(wc, v2.w, acc.w);
    acc.x = fmaf(wd, v3.x, acc.x); acc.y = fmaf(wd, v3.y, acc.y);
    acc.z = fmaf(wd, v3.z, acc.z); acc.w = fmaf(wd, v3.w, acc.w);

    // ---- rare tail: h >= PF (~4% of batches), batched guarded loads ----
    for (int t0 = PF; t0 <= h; t0 += 4) {
        float4 u[4];
        #pragma unroll
        for (int i = 0; i < 4; i++) {
            const int t = t0 + i;
            u[i] = (t < T_DIM) ? __ldcs(base + (size_t)t * D4)
                               : make_float4(0.f, 0.f, 0.f, 0.f);
        }
        #pragma unroll
        for (int i = 0; i < 4; i++) {
            const int t = t0 + i;
            // t is warp-uniform: fetch weight from owning lane
            float wt = __shfl_sync(FULL, (t & 1) ? w1 : w0, (t >> 1) & 31);
            if (t >= T_DIM) wt = 0.0f;
            acc.x = fmaf(wt, u[i].x, acc.x);
            acc.y = fmaf(wt, u[i].y, acc.y);
            acc.z = fmaf(wt, u[i].z, acc.z);
            acc.w = fmaf(wt, u[i].w, acc.w);
        }
    }

    reinterpret_cast<float4*>(final_out)[(size_t)b * D4 + d4] = acc;
}

// ---------------------------------------------------------------------------
// kernel_launch
// Inputs: halt_probs [B,T,1], outputs [B,T,D], step_weights [B,T]  (fp32)
// Output: concat(final_output [B*D], ponder_cost [B], weights [B*T]) fp32
// ---------------------------------------------------------------------------
extern "C" void kernel_launch(void* const* d_in, const int* in_sizes, int n_in,
                              void* d_out, int out_size)
{
    const float* halt_probs   = (const float*)d_in[0];
    const float* outputs      = (const float*)d_in[1];
    const float* step_weights = (const float*)d_in[2];

    float* out         = (float*)d_out;
    float* final_out   = out;                              // [B,D]
    float* ponder_out  = out + (size_t)B_DIM * D_DIM;      // [B]
    float* weights_out = ponder_out + B_DIM;               // [B,T]

    act_sparse_kernel<<<B_DIM * BLOCKS_PER_B, THREADS>>>(
        halt_probs, outputs, step_weights,
        final_out, ponder_out, weights_out);
}

// round 16
// speedup vs baseline: 1.3023x; 1.0047x over previous
#include <cuda_runtime.h>

#define B_DIM 256
#define T_DIM 64
#define D_DIM 2048
#define THRESHOLD 0.99f
#define EPSILON 0.01f

#define THREADS 128
#define D4 (D_DIM / 4)                    // 512 float4 per row
#define BLOCKS_PER_B 4                    // 4 chunks of 128 float4 columns
#define PF 4                              // prefetch depth (covers h<=3: ~96%)

// ---------------------------------------------------------------------------
// Sparse ACT kernel, barrier-free (final; measured-best configuration).
//
// Key insight: the ACT weights are exactly zero for t > h (halt step), and
// with U(0,1) halt probs h ~ 2-3, so only ~10MB of the 128MB `outputs`
// tensor contributes. Each warp redundantly computes the halting weights
// with a shuffle scan (no smem handoff, no __syncthreads); the 4-row
// prefetch is issued FIRST so all 6 global loads per thread overlap in the
// L1tex queue (gating row loads on weight data costs a full extra memory
// round-trip -- measured +3us in R12/R14). Rare h>=4 tail uses batched
// guarded loads. Summation order over nonzero terms matches the dense
// reference exactly (zeros contribute nothing).
// grid = B*4 = 1024, block = 128.
// ---------------------------------------------------------------------------
__global__ __launch_bounds__(THREADS)
void act_sparse_kernel(const float* __restrict__ halt_probs,   // [B,T]
                       const float* __restrict__ outputs,      // [B,T,D]
                       const float* __restrict__ step_weights, // [B,T]
                       float* __restrict__ final_out,          // [B,D]
                       float* __restrict__ out_ponder,         // [B]
                       float* __restrict__ out_weights)        // [B,T]
{
    const int b     = blockIdx.x / BLOCKS_PER_B;
    const int chunk = blockIdx.x % BLOCKS_PER_B;
    const int tid   = threadIdx.x;
    const int warp  = tid >> 5;
    const int lane  = tid & 31;
    const unsigned FULL = 0xFFFFFFFFu;

    const int d4 = chunk * THREADS + tid;   // float4 column in [0, D4)
    const float4* __restrict__ base =
        reinterpret_cast<const float4*>(outputs) + (size_t)b * T_DIM * D4 + d4;

    // ---- issue row prefetch FIRST (independent of weights) ----
    float4 v0 = __ldcs(base + 0 * D4);
    float4 v1 = __ldcs(base + 1 * D4);
    float4 v2 = __ldcs(base + 2 * D4);
    float4 v3 = __ldcs(base + 3 * D4);

    // ---- per-warp redundant weight computation (overlaps row loads) ----
    // lane owns t = 2*lane, 2*lane+1
    const float2 p  = reinterpret_cast<const float2*>(halt_probs   + b * T_DIM)[lane];
    const float2 sw = reinterpret_cast<const float2*>(step_weights + b * T_DIM)[lane];

    // inclusive scan of pair sums
    const float pairsum = p.x + p.y;
    float s = pairsum;
    #pragma unroll
    for (int o = 1; o < 32; o <<= 1) {
        float n = __shfl_up_sync(FULL, s, o);
        if (lane >= o) s += n;
    }
    const float excl = s - pairsum;     // cumsum before t=2*lane
    const float cum0 = excl + p.x;      // cumsum at t=2*lane
    const float cum1 = s;               // cumsum at t=2*lane+1

    const unsigned m0 = __ballot_sync(FULL, cum0 >= THRESHOLD);
    const unsigned m1 = __ballot_sync(FULL, cum1 >= THRESHOLD);
    const int c0 = m0 ? 2 * (__ffs(m0) - 1)     : T_DIM;
    const int c1 = m1 ? 2 * (__ffs(m1) - 1) + 1 : T_DIM;
    int h = min(c0, c1);
    if (h >= T_DIM) h = T_DIM - 1;

    const int   hl   = h >> 1;
    const int   hodd = h & 1;
    const float cum_at = __shfl_sync(FULL, hodd ? cum1 : cum0, hl);
    const float p_at   = __shfl_sync(FULL, hodd ? p.y  : p.x,  hl);
    const float rem    = 1.0f - cum_at + p_at;

    const int t0i = 2 * lane, t1i = 2 * lane + 1;
    float w0 = (t0i < h) ? p.x : ((t0i == h) ? rem : 0.0f);
    float w1 = (t1i < h) ? p.y : ((t1i == h) ? rem : 0.0f);
    w0 *= sw.x; w1 *= sw.y;

    float ws = w0 + w1;
    #pragma unroll
    for (int o = 16; o; o >>= 1) ws += __shfl_xor_sync(FULL, ws, o);
    const float inv = 1.0f / fmaxf(ws, EPSILON);
    w0 *= inv; w1 *= inv;

    // weights + ponder outputs: one warp of one block per batch
    if (chunk == 0 && warp == 0) {
        reinterpret_cast<float2*>(out_weights + b * T_DIM)[lane] =
            make_float2(w0, w1);
        float pc = w0 * (float)(t0i + 1) + w1 * (float)(t1i + 1);
        #pragma unroll
        for (int o = 16; o; o >>= 1) pc += __shfl_xor_sync(FULL, pc, o);
        if (lane == 0) out_ponder[b] = pc;
    }

    // broadcast first-4 weights from lanes 0,1
    const float wa = __shfl_sync(FULL, w0, 0);   // t=0
    const float wb = __shfl_sync(FULL, w1, 0);   // t=1
    const float wc = __shfl_sync(FULL, w0, 1);   // t=2
    const float wd = __shfl_sync(FULL, w1, 1);   // t=3

    // ---- consume prefetched rows ----
    float4 acc;
    acc.x = wa * v0.x; acc.y = wa * v0.y; acc.z = wa * v0.z; acc.w = wa * v0.w;
    acc.x = fmaf(wb, v1.x, acc.x); acc.y = fmaf(wb, v1.y, acc.y);
    acc.z = fmaf(wb, v1.z, acc.z); acc.w = fmaf(wb, v1.w, acc.w);
    acc.x = fmaf(wc, v2.x, acc.x); acc.y = fmaf(wc, v2.y, acc.y);
    acc.z = fmaf(wc, v2.z, acc.z); acc.w = fmaf(wc, v2.w, acc.w);
    acc.x = fmaf(wd, v3.x, acc.x); acc.y = fmaf(wd, v3.y, acc.y);
    acc.z = fmaf(wd, v3.z, acc.z); acc.w = fmaf(wd, v3.w, acc.w);

    // ---- rare tail: h >= PF (~4% of batches), batched guarded loads ----
    for (int t0 = PF; t0 <= h; t0 += 4) {
        float4 u[4];
        #pragma unroll
        for (int i = 0; i < 4; i++) {
            const int t = t0 + i;
            u[i] = (t < T_DIM) ? __ldcs(base + (size_t)t * D4)
                               : make_float4(0.f, 0.f, 0.f, 0.f);
        }
        #pragma unroll
        for (int i = 0; i < 4; i++) {
            const int t = t0 + i;
            // t is warp-uniform: fetch weight from owning lane
            float wt = __shfl_sync(FULL, (t & 1) ? w1 : w0, (t >> 1) & 31);
            if (t >= T_DIM) wt = 0.0f;
            acc.x = fmaf(wt, u[i].x, acc.x);
            acc.y = fmaf(wt, u[i].y, acc.y);
            acc.z = fmaf(wt, u[i].z, acc.z);
            acc.w = fmaf(wt, u[i].w, acc.w);
        }
    }

    reinterpret_cast<float4*>(final_out)[(size_t)b * D4 + d4] = acc;
}

// ---------------------------------------------------------------------------
// kernel_launch
// Inputs: halt_probs [B,T,1], outputs [B,T,D], step_weights [B,T]  (fp32)
// Output: concat(final_output [B*D], ponder_cost [B], weights [B*T]) fp32
// ---------------------------------------------------------------------------
extern "C" void kernel_launch(void* const* d_in, const int* in_sizes, int n_in,
                              void* d_out, int out_size)
{
    const float* halt_probs   = (const float*)d_in[0];
    const float* outputs      = (const float*)d_in[1];
    const float* step_weights = (const float*)d_in[2];

    float* out         = (float*)d_out;
    float* final_out   = out;                              // [B,D]
    float* ponder_out  = out + (size_t)B_DIM * D_DIM;      // [B]
    float* weights_out = ponder_out + B_DIM;               // [B,T]

    act_sparse_kernel<<<B_DIM * BLOCKS_PER_B, THREADS>>>(
        halt_probs, outputs, step_weights,
        final_out, ponder_out, weights_out);
}